// round 8
// baseline (speedup 1.0000x reference)
#include <cuda_runtime.h>
#include <cuda_bf16.h>

#define INPUT_DIM 4
#define H1 64
#define H2 32
#define BATCH 64
#define SEQ 4096
#define RING 8
#define NT_L1 512            // 2 lanes per layer-1 gate (256 gates)
#define NT_L2 256            // 2 lanes per layer-2 gate (128 gates)
#define NTHREADS (NT_L1 + NT_L2)   // 768

typedef unsigned long long ull;

// ---- packed f32x2 helpers ----
__device__ __forceinline__ ull pk2(float a, float b) {
    ull r; asm("mov.b64 %0, {%1, %2};" : "=l"(r) : "f"(a), "f"(b)); return r;
}
__device__ __forceinline__ void upk2(ull v, float& a, float& b) {
    asm("mov.b64 {%0, %1}, %2;" : "=f"(a), "=f"(b) : "l"(v));
}
__device__ __forceinline__ ull fma2(ull a, ull b, ull c) {
    ull d; asm("fma.rn.f32x2 %0, %1, %2, %3;" : "=l"(d) : "l"(a), "l"(b), "l"(c)); return d;
}
__device__ __forceinline__ ull add2(ull a, ull b) {
    ull d; asm("add.rn.f32x2 %0, %1, %2;" : "=l"(d) : "l"(a), "l"(b)); return d;
}
__device__ __forceinline__ float tanh_approx(float x) {
    float y; asm("tanh.approx.f32 %0, %1;" : "=f"(y) : "f"(x)); return y;
}
__device__ __forceinline__ int ld_acq(const int* p) {
    int v; asm volatile("ld.acquire.cta.b32 %0, [%1];" : "=r"(v) : "l"(p) : "memory"); return v;
}
__device__ __forceinline__ void st_rel(int* p, int v) {
    asm volatile("st.release.cta.b32 [%0], %1;" :: "l"(p), "r"(v) : "memory");
}
__device__ __forceinline__ void bar_sync(int id, int cnt) {
    asm volatile("bar.sync %0, %1;" :: "r"(id), "r"(cnt) : "memory");
}

__global__ void __launch_bounds__(NTHREADS, 1)
lstm2_kernel(const float* __restrict__ x,
             const float* __restrict__ W_ih1, const float* __restrict__ W_hh1,
             const float* __restrict__ b_ih1, const float* __restrict__ b_hh1,
             const float* __restrict__ W_ih2, const float* __restrict__ W_hh2,
             const float* __restrict__ b_ih2, const float* __restrict__ b_hh2,
             float* __restrict__ out)
{
    const int b   = blockIdx.x;
    const int tid = threadIdx.x;

    __shared__ __align__(16) float h1ring[RING][H1];
    __shared__ __align__(16) float h2buf[2][H2];
    __shared__ int l1_done;
    __shared__ int l2_done;

    if (tid == 0) { l1_done = -1; l2_done = -1; }
    if (tid < H1) h1ring[RING - 1][tid] = 0.0f;   // h1(-1)=0 in slot RING-1
    if (tid < H2) h2buf[0][tid] = 0.0f;           // h2(-1)=0 in buf 0
    __syncthreads();

    if (tid < NT_L1) {
        // ================= Layer 1: 2 lanes per gate =================
        // gs = tid>>1 (gate slot), half = tid&1; unit u = gs>>2, gate q = gs&3.
        // 8-lane group per unit: lane bits = [unit...|q1|q0|half]
        const int half = tid & 1;
        const int gs   = tid >> 1;
        const int u    = gs >> 2;
        const int q    = gs & 3;
        const int row  = q * H1 + u;

        const float aS = (q == 2) ? 1.0f : 0.5f;   // g: tanh ; others: sigmoid
        const float aA = (q == 2) ? 1.0f : 0.5f;
        const float aB = (q == 2) ? 0.0f : 0.5f;

        // half-dot weights: h[half*32 .. half*32+31]
        ull wh[16];
        {
            const float2* whh = reinterpret_cast<const float2*>(W_hh1 + row * H1 + half * 32);
            #pragma unroll
            for (int k = 0; k < 16; ++k) { const float2 v = whh[k]; wh[k] = pk2(v.x, v.y); }
        }
        // x-part handled by half==1 lanes only (zeros otherwise); bias on half==0
        ull wx0 = 0ull, wx1 = 0ull;
        if (half) {
            const float2* wih = reinterpret_cast<const float2*>(W_ih1 + row * INPUT_DIM);
            float2 v = wih[0]; wx0 = pk2(v.x, v.y);
            v = wih[1];        wx1 = pk2(v.x, v.y);
        }
        const float bias = half ? 0.0f : (b_ih1[row] + b_hh1[row]);

        const float4* xb4 = reinterpret_cast<const float4*>(x + (size_t)b * SEQ * INPUT_DIM);
        float c = 0.0f;                 // valid on (tid&7)==0 lanes
        int consumed = -1;
        float4 xv = __ldg(xb4);         // x(0)

        #pragma unroll 1
        for (int t = 0; t < SEQ; ++t) {
            const int tn = (t + 1 < SEQ) ? (t + 1) : t;
            const float4 xv_next = __ldg(xb4 + tn);

            // batched backpressure: every 4 steps ensure l2_done >= t-5
            // (covers writes t..t+3, which overwrite h1(t-8..t-5))
            if ((t & 3) == 0 && t >= RING) {
                if (consumed < t - 5) {
                    do { consumed = ld_acq(&l2_done); } while (consumed < t - 5);
                }
            }

            const ulonglong2* hv = reinterpret_cast<const ulonglong2*>(
                h1ring[(t + RING - 1) & (RING - 1)] + half * 32);

            ull a0 = pk2(bias, 0.0f), a1 = 0ull, a2 = 0ull, a3 = 0ull;
            #pragma unroll
            for (int kk = 0; kk < 4; ++kk) {
                const ulonglong2 A = hv[2 * kk];
                const ulonglong2 B = hv[2 * kk + 1];
                a0 = fma2(wh[4 * kk + 0], A.x, a0);
                a1 = fma2(wh[4 * kk + 1], A.y, a1);
                a2 = fma2(wh[4 * kk + 2], B.x, a2);
                a3 = fma2(wh[4 * kk + 3], B.y, a3);
            }
            a0 = fma2(wx0, pk2(xv.x, xv.y), a0);
            a1 = fma2(wx1, pk2(xv.z, xv.w), a1);
            a0 = add2(add2(a0, a1), add2(a2, a3));
            float lo, hi; upk2(a0, lo, hi);
            const float part = lo + hi;
            const float raw  = part + __shfl_xor_sync(0xffffffffu, part, 1);

            const float act = __fmaf_rn(aA, tanh_approx(aS * raw), aB);
            // gather gates into the q==0 lanes: f at ^2, g at ^4, o at ^6
            const float fA = __shfl_xor_sync(0xffffffffu, act, 2);
            const float gA = __shfl_xor_sync(0xffffffffu, act, 4);
            const float oA = __shfl_xor_sync(0xffffffffu, act, 6);
            c = __fmaf_rn(fA, c, act * gA);        // meaningful on (tid&7)==0
            const float h = oA * tanh_approx(c);
            if ((tid & 7) == 0) h1ring[t & (RING - 1)][u] = h;

            bar_sync(1, NT_L1);
            if (tid == 0) st_rel(&l1_done, t);
            xv = xv_next;
        }
    } else {
        // ================= Layer 2: 2 lanes per gate =================
        const int p    = tid - NT_L1;
        const int half = p & 1;
        const int gs   = p >> 1;       // 0..127
        const int u    = gs >> 2;      // 0..31
        const int q    = gs & 3;
        const int row  = q * H2 + u;

        const float aS = (q == 2) ? 1.0f : 0.5f;
        const float aA = (q == 2) ? 1.0f : 0.5f;
        const float aB = (q == 2) ? 0.0f : 0.5f;

        ull wih[16], whh[8];
        {
            const float2* a = reinterpret_cast<const float2*>(W_ih2 + row * H1 + half * 32);
            #pragma unroll
            for (int k = 0; k < 16; ++k) { const float2 v = a[k]; wih[k] = pk2(v.x, v.y); }
            const float2* c2 = reinterpret_cast<const float2*>(W_hh2 + row * H2 + half * 16);
            #pragma unroll
            for (int k = 0; k < 8; ++k) { const float2 v = c2[k]; whh[k] = pk2(v.x, v.y); }
        }
        const float bias = half ? 0.0f : (b_ih2[row] + b_hh2[row]);
        float* outb = out + (size_t)b * SEQ * H2;

        float c = 0.0f;
        int avail = -1;

        #pragma unroll 1
        for (int t = 0; t < SEQ; ++t) {
            if (avail < t) {
                do { avail = ld_acq(&l1_done); } while (avail < t);
            }

            const ulonglong2* hv = reinterpret_cast<const ulonglong2*>(
                h1ring[t & (RING - 1)] + half * 32);
            const ulonglong2* gv = reinterpret_cast<const ulonglong2*>(
                h2buf[t & 1] + half * 16);

            ull a0 = pk2(bias, 0.0f), a1 = 0ull, a2 = 0ull, a3 = 0ull;
            #pragma unroll
            for (int kk = 0; kk < 4; ++kk) {
                const ulonglong2 A = hv[2 * kk];
                const ulonglong2 B = hv[2 * kk + 1];
                a0 = fma2(wih[4 * kk + 0], A.x, a0);
                a1 = fma2(wih[4 * kk + 1], A.y, a1);
                a2 = fma2(wih[4 * kk + 2], B.x, a2);
                a3 = fma2(wih[4 * kk + 3], B.y, a3);
            }
            #pragma unroll
            for (int kk = 0; kk < 2; ++kk) {
                const ulonglong2 A = gv[2 * kk];
                const ulonglong2 B = gv[2 * kk + 1];
                a0 = fma2(whh[4 * kk + 0], A.x, a0);
                a1 = fma2(whh[4 * kk + 1], A.y, a1);
                a2 = fma2(whh[4 * kk + 2], B.x, a2);
                a3 = fma2(whh[4 * kk + 3], B.y, a3);
            }
            a0 = add2(add2(a0, a1), add2(a2, a3));
            float lo, hi; upk2(a0, lo, hi);
            const float part = lo + hi;
            const float raw  = part + __shfl_xor_sync(0xffffffffu, part, 1);

            const float act = __fmaf_rn(aA, tanh_approx(aS * raw), aB);
            const float fA = __shfl_xor_sync(0xffffffffu, act, 2);
            const float gA = __shfl_xor_sync(0xffffffffu, act, 4);
            const float oA = __shfl_xor_sync(0xffffffffu, act, 6);
            c = __fmaf_rn(fA, c, act * gA);
            const float h = oA * tanh_approx(c);

            if ((p & 7) == 0) {
                h2buf[(t + 1) & 1][u] = h;
                outb[(size_t)t * H2 + u] = h;
            }
            bar_sync(2, NT_L2);
            if (tid == NT_L1) st_rel(&l2_done, t);
        }
    }
}

extern "C" void kernel_launch(void* const* d_in, const int* in_sizes, int n_in,
                              void* d_out, int out_size) {
    const float* x     = (const float*)d_in[0];
    const float* W_ih1 = (const float*)d_in[1];
    const float* W_hh1 = (const float*)d_in[2];
    const float* b_ih1 = (const float*)d_in[3];
    const float* b_hh1 = (const float*)d_in[4];
    const float* W_ih2 = (const float*)d_in[5];
    const float* W_hh2 = (const float*)d_in[6];
    const float* b_ih2 = (const float*)d_in[7];
    const float* b_hh2 = (const float*)d_in[8];
    float* out = (float*)d_out;

    lstm2_kernel<<<BATCH, NTHREADS>>>(x, W_ih1, W_hh1, b_ih1, b_hh1,
                                      W_ih2, W_hh2, b_ih2, b_hh2, out);
}

// round 9
// speedup vs baseline: 1.6352x; 1.6352x over previous
#include <cuda_runtime.h>
#include <cuda_bf16.h>

#define INPUT_DIM 4
#define H1 64
#define H2 32
#define BATCH 64
#define SEQ 4096

#define NT_L1 128           // layer-1: 2 gates per thread
#define NT_L2 128           // layer-2: 1 gate per thread
#define NTHREADS (NT_L1 + NT_L2)
#define RING 8

typedef unsigned long long ull;

// ---- packed f32x2 helpers ----
__device__ __forceinline__ ull pk2(float a, float b) {
    ull r; asm("mov.b64 %0, {%1, %2};" : "=l"(r) : "f"(a), "f"(b)); return r;
}
__device__ __forceinline__ void upk2(ull v, float& a, float& b) {
    asm("mov.b64 {%0, %1}, %2;" : "=f"(a), "=f"(b) : "l"(v));
}
__device__ __forceinline__ ull fma2(ull a, ull b, ull c) {
    ull d; asm("fma.rn.f32x2 %0, %1, %2, %3;" : "=l"(d) : "l"(a), "l"(b), "l"(c)); return d;
}
__device__ __forceinline__ ull add2(ull a, ull b) {
    ull d; asm("add.rn.f32x2 %0, %1, %2;" : "=l"(d) : "l"(a), "l"(b)); return d;
}
__device__ __forceinline__ float tanh_approx(float x) {
    float y; asm("tanh.approx.f32 %0, %1;" : "=f"(y) : "f"(x)); return y;
}
__device__ __forceinline__ void bar_sync(int id, int cnt) {
    asm volatile("bar.sync %0, %1;" :: "r"(id), "r"(cnt) : "memory");
}

// ---- mbarrier (shared, cta scope) ----
__device__ __forceinline__ unsigned s2u(const void* p) {
    unsigned a;
    asm("{ .reg .u64 t; cvta.to.shared.u64 t, %1; cvt.u32.u64 %0, t; }"
        : "=r"(a) : "l"(p));
    return a;
}
__device__ __forceinline__ void mbar_init(unsigned saddr, unsigned cnt) {
    asm volatile("mbarrier.init.shared.b64 [%0], %1;" :: "r"(saddr), "r"(cnt) : "memory");
}
__device__ __forceinline__ void mbar_arrive(unsigned saddr) {
    asm volatile("mbarrier.arrive.release.cta.shared::cta.b64 _, [%0];"
                 :: "r"(saddr) : "memory");
}
// HW-sleep wait (no issue-slot theft while suspended)
__device__ __forceinline__ void mbar_wait(unsigned saddr, unsigned parity) {
    unsigned done;
    asm volatile(
        "{\n\t.reg .pred p;\n\t"
        "mbarrier.try_wait.parity.acquire.cta.shared::cta.b64 p, [%1], %2, 0x989680;\n\t"
        "selp.b32 %0, 1, 0, p;\n\t}"
        : "=r"(done) : "r"(saddr), "r"(parity) : "memory");
    while (!done) {
        asm volatile(
            "{\n\t.reg .pred p;\n\t"
            "mbarrier.try_wait.parity.acquire.cta.shared::cta.b64 p, [%1], %2, 0x989680;\n\t"
            "selp.b32 %0, 1, 0, p;\n\t}"
            : "=r"(done) : "r"(saddr), "r"(parity) : "memory");
    }
}

__global__ void __launch_bounds__(NTHREADS, 1)
lstm2_kernel(const float* __restrict__ x,
             const float* __restrict__ W_ih1, const float* __restrict__ W_hh1,
             const float* __restrict__ b_ih1, const float* __restrict__ b_hh1,
             const float* __restrict__ W_ih2, const float* __restrict__ W_hh2,
             const float* __restrict__ b_ih2, const float* __restrict__ b_hh2,
             float* __restrict__ out)
{
    const int b   = blockIdx.x;
    const int tid = threadIdx.x;

    __shared__ __align__(16) float h1ring[RING][H1];
    __shared__ __align__(16) float h2buf[2][H2];
    __shared__ __align__(8)  ull full_mb[RING];  // L1 -> L2: h1(t) ready
    __shared__ __align__(8)  ull free_mb[RING];  // L2 -> L1: ring slot freed

    const bool isL1 = tid < NT_L1;

    if (tid == 0) {
        #pragma unroll
        for (int s = 0; s < RING; ++s) {
            mbar_init(s2u(&full_mb[s]), 1);
            mbar_init(s2u(&free_mb[s]), 1);
        }
    }
    if (isL1 && (tid & 1)) h1ring[RING - 1][tid >> 1] = 0.0f;          // h1(-1)=0
    if (!isL1 && (((tid - NT_L1) & 3) == 0)) h2buf[0][(tid - NT_L1) >> 2] = 0.0f;
    __syncthreads();

    if (isL1) {
        // ======== Layer 1: 2 gates per thread ========
        const int u   = tid >> 1;
        const int par = tid & 1;
        const int rowA = par * H1 + u;        // par0: i, par1: f
        const int rowB = (2 + par) * H1 + u;  // par0: g, par1: o

        const float bS = par ? 0.5f : 1.0f;   // gateB: g->tanh, o->sigmoid
        const float bA = par ? 0.5f : 1.0f;
        const float bB = par ? 0.5f : 0.0f;

        ull wA[32], wB[32], xA0, xA1, xB0, xB1;
        {
            const float2* whhA = reinterpret_cast<const float2*>(W_hh1 + rowA * H1);
            const float2* whhB = reinterpret_cast<const float2*>(W_hh1 + rowB * H1);
            #pragma unroll
            for (int k = 0; k < 32; ++k) {
                float2 v = whhA[k]; wA[k] = pk2(v.x, v.y);
                float2 w = whhB[k]; wB[k] = pk2(w.x, w.y);
            }
            const float2* wihA = reinterpret_cast<const float2*>(W_ih1 + rowA * INPUT_DIM);
            const float2* wihB = reinterpret_cast<const float2*>(W_ih1 + rowB * INPUT_DIM);
            float2 v;
            v = wihA[0]; xA0 = pk2(v.x, v.y);
            v = wihA[1]; xA1 = pk2(v.x, v.y);
            v = wihB[0]; xB0 = pk2(v.x, v.y);
            v = wihB[1]; xB1 = pk2(v.x, v.y);
        }
        const float biasA = b_ih1[rowA] + b_hh1[rowA];
        const float biasB = b_ih1[rowB] + b_hh1[rowB];

        const float4* xb4 = reinterpret_cast<const float4*>(x + (size_t)b * SEQ * INPUT_DIM);
        float c = 0.0f;          // valid in par==1 lanes
        float4 xv = __ldg(xb4);  // x(0)

        #pragma unroll 1
        for (int t = 0; t < SEQ; ++t) {
            const int tn = (t + 1 < SEQ) ? (t + 1) : t;
            const float4 xv_next = __ldg(xb4 + tn);

            // backpressure: slot t&7 overwrites h1(t-8); wait until L2 freed it.
            // free_mb[s] k-th arrive happens at L2 step s+8k; phase for t-8 is ((t>>3)-1)&1
            if (t >= RING) {
                mbar_wait(s2u(&free_mb[t & (RING - 1)]), (unsigned)(((t >> 3) - 1) & 1));
            }

            const ulonglong2* hv =
                reinterpret_cast<const ulonglong2*>(h1ring[(t + RING - 1) & (RING - 1)]);
            const ull xp0 = pk2(xv.x, xv.y);
            const ull xp1 = pk2(xv.z, xv.w);

            ull a0 = pk2(biasA, 0.0f), a1 = 0ull, a2 = 0ull, a3 = 0ull;
            ull d0 = pk2(biasB, 0.0f), d1 = 0ull, d2 = 0ull, d3 = 0ull;
            #pragma unroll
            for (int kk = 0; kk < 8; ++kk) {
                const ulonglong2 hA = hv[2 * kk];
                const ulonglong2 hB = hv[2 * kk + 1];
                a0 = fma2(wA[4 * kk + 0], hA.x, a0);
                d0 = fma2(wB[4 * kk + 0], hA.x, d0);
                a1 = fma2(wA[4 * kk + 1], hA.y, a1);
                d1 = fma2(wB[4 * kk + 1], hA.y, d1);
                a2 = fma2(wA[4 * kk + 2], hB.x, a2);
                d2 = fma2(wB[4 * kk + 2], hB.x, d2);
                a3 = fma2(wA[4 * kk + 3], hB.y, a3);
                d3 = fma2(wB[4 * kk + 3], hB.y, d3);
            }
            a0 = fma2(xA0, xp0, a0); a1 = fma2(xA1, xp1, a1);
            d0 = fma2(xB0, xp0, d0); d1 = fma2(xB1, xp1, d1);
            a0 = add2(add2(a0, a1), add2(a2, a3));
            d0 = add2(add2(d0, d1), add2(d2, d3));
            float alo, ahi, dlo, dhi;
            upk2(a0, alo, ahi); upk2(d0, dlo, dhi);
            const float rawA = alo + ahi;
            const float rawB = dlo + dhi;

            const float sA = __fmaf_rn(0.5f, tanh_approx(0.5f * rawA), 0.5f); // sigmoid
            const float sB = __fmaf_rn(bA, tanh_approx(bS * rawB), bB);

            const float val = sA * sB;                          // par0: i*g
            const float ig  = __shfl_xor_sync(0xffffffffu, val, 1);
            c = __fmaf_rn(sA, c, ig);                           // par1: c=f*c+i*g
            const float h = sB * tanh_approx(c);                // par1: h=o*tanh(c)
            if (par) h1ring[t & (RING - 1)][u] = h;

            bar_sync(1, NT_L1);
            if (tid == 0) mbar_arrive(s2u(&full_mb[t & (RING - 1)]));  // publish h1(t)
            xv = xv_next;
        }
    } else {
        // ======== Layer 2: 1 gate per thread ========
        const int p = tid - NT_L1;
        const int u = p >> 2;
        const int q = p & 3;
        const float actS = (q == 2) ? 1.0f : 0.5f;
        const float actA = (q == 2) ? 1.0f : 0.5f;
        const float actB = (q == 2) ? 0.0f : 0.5f;

        const int g = q * H2 + u;
        ull w2[48];
        {
            const float2* wih = reinterpret_cast<const float2*>(W_ih2 + g * H1);
            #pragma unroll
            for (int k = 0; k < 32; ++k) { const float2 v = wih[k]; w2[k] = pk2(v.x, v.y); }
            const float2* whh = reinterpret_cast<const float2*>(W_hh2 + g * H2);
            #pragma unroll
            for (int k = 0; k < 16; ++k) { const float2 v = whh[k]; w2[32 + k] = pk2(v.x, v.y); }
        }
        const float bias = b_ih2[g] + b_hh2[g];
        float* outb = out + (size_t)b * SEQ * H2;

        float c = 0.0f;

        #pragma unroll 1
        for (int t = 0; t < SEQ; ++t) {
            // wait for h1(t): full_mb[t&7], k-th arrive at L1 step (t&7)+8k -> phase (t>>3)&1
            mbar_wait(s2u(&full_mb[t & (RING - 1)]), (unsigned)((t >> 3) & 1));

            const ulonglong2* hv = reinterpret_cast<const ulonglong2*>(h1ring[t & (RING - 1)]);
            const ulonglong2* gv = reinterpret_cast<const ulonglong2*>(h2buf[t & 1]);

            ull a0 = pk2(bias, 0.0f);
            ull a1 = 0ull, a2 = 0ull, a3 = 0ull;
            #pragma unroll
            for (int kk = 0; kk < 8; ++kk) {
                const ulonglong2 hA = hv[2 * kk];
                const ulonglong2 hB = hv[2 * kk + 1];
                a0 = fma2(w2[4 * kk + 0], hA.x, a0);
                a1 = fma2(w2[4 * kk + 1], hA.y, a1);
                a2 = fma2(w2[4 * kk + 2], hB.x, a2);
                a3 = fma2(w2[4 * kk + 3], hB.y, a3);
            }
            #pragma unroll
            for (int kk = 0; kk < 4; ++kk) {
                const ulonglong2 hA = gv[2 * kk];
                const ulonglong2 hB = gv[2 * kk + 1];
                a0 = fma2(w2[32 + 4 * kk + 0], hA.x, a0);
                a1 = fma2(w2[32 + 4 * kk + 1], hA.y, a1);
                a2 = fma2(w2[32 + 4 * kk + 2], hB.x, a2);
                a3 = fma2(w2[32 + 4 * kk + 3], hB.y, a3);
            }
            a0 = add2(add2(a0, a1), add2(a2, a3));
            float lo, hi; upk2(a0, lo, hi);
            const float raw = lo + hi;

            const float act = __fmaf_rn(actA, tanh_approx(actS * raw), actB);
            const float v1 = __shfl_xor_sync(0xffffffffu, act, 1);
            const float v2 = __shfl_xor_sync(0xffffffffu, act, 2);
            const float v3 = __shfl_xor_sync(0xffffffffu, act, 3);
            c = __fmaf_rn(v1, c, act * v2);
            const float h = v3 * tanh_approx(c);

            if (q == 0) {
                h2buf[(t + 1) & 1][u] = h;
                outb[(size_t)t * H2 + u] = h;
            }
            bar_sync(2, NT_L2);
            if (tid == NT_L1) mbar_arrive(s2u(&free_mb[t & (RING - 1)]));  // free slot t
        }
    }
}

extern "C" void kernel_launch(void* const* d_in, const int* in_sizes, int n_in,
                              void* d_out, int out_size) {
    const float* x     = (const float*)d_in[0];
    const float* W_ih1 = (const float*)d_in[1];
    const float* W_hh1 = (const float*)d_in[2];
    const float* b_ih1 = (const float*)d_in[3];
    const float* b_hh1 = (const float*)d_in[4];
    const float* W_ih2 = (const float*)d_in[5];
    const float* W_hh2 = (const float*)d_in[6];
    const float* b_ih2 = (const float*)d_in[7];
    const float* b_hh2 = (const float*)d_in[8];
    float* out = (float*)d_out;

    lstm2_kernel<<<BATCH, NTHREADS>>>(x, W_ih1, W_hh1, b_ih1, b_hh1,
                                      W_ih2, W_hh2, b_ih2, b_hh2, out);
}

// round 10
// speedup vs baseline: 1.9804x; 1.2111x over previous
#include <cuda_runtime.h>
#include <cuda_bf16.h>

#define INPUT_DIM 4
#define H1 64
#define H2 32
#define BATCH 64
#define SEQ 4096

#define NT_L2 128           // tids 0..127   (low wid -> lower arbiter priority)
#define NT_L1 128           // tids 128..255 (high wid -> priority; critical path)
#define NTHREADS (NT_L1 + NT_L2)
#define RING 8              // h1 ring depth; slot s uses named barrier id 2+s

typedef unsigned long long ull;

// ---- packed f32x2 helpers ----
__device__ __forceinline__ ull pk2(float a, float b) {
    ull r; asm("mov.b64 %0, {%1, %2};" : "=l"(r) : "f"(a), "f"(b)); return r;
}
__device__ __forceinline__ void upk2(ull v, float& a, float& b) {
    asm("mov.b64 {%0, %1}, %2;" : "=f"(a), "=f"(b) : "l"(v));
}
__device__ __forceinline__ ull fma2(ull a, ull b, ull c) {
    ull d; asm("fma.rn.f32x2 %0, %1, %2, %3;" : "=l"(d) : "l"(a), "l"(b), "l"(c)); return d;
}
__device__ __forceinline__ ull add2(ull a, ull b) {
    ull d; asm("add.rn.f32x2 %0, %1, %2;" : "=l"(d) : "l"(a), "l"(b)); return d;
}
__device__ __forceinline__ float tanh_approx(float x) {
    float y; asm("tanh.approx.f32 %0, %1;" : "=f"(y) : "f"(x)); return y;
}
__device__ __forceinline__ int ld_acq(const int* p) {
    int v; asm volatile("ld.acquire.cta.b32 %0, [%1];" : "=r"(v) : "l"(p) : "memory"); return v;
}
__device__ __forceinline__ void st_rel(int* p, int v) {
    asm volatile("st.release.cta.b32 [%0], %1;" :: "l"(p), "r"(v) : "memory");
}
__device__ __forceinline__ void bar_sync(int id, int cnt) {
    asm volatile("bar.sync %0, %1;" :: "r"(id), "r"(cnt) : "memory");
}
__device__ __forceinline__ void bar_arrive(int id, int cnt) {
    asm volatile("bar.arrive %0, %1;" :: "r"(id), "r"(cnt) : "memory");
}

__global__ void __launch_bounds__(NTHREADS, 1)
lstm2_kernel(const float* __restrict__ x,
             const float* __restrict__ W_ih1, const float* __restrict__ W_hh1,
             const float* __restrict__ b_ih1, const float* __restrict__ b_hh1,
             const float* __restrict__ W_ih2, const float* __restrict__ W_hh2,
             const float* __restrict__ b_ih2, const float* __restrict__ b_hh2,
             float* __restrict__ out)
{
    const int b   = blockIdx.x;
    const int tid = threadIdx.x;

    __shared__ __align__(16) float h1ring[RING][H1];
    __shared__ __align__(16) float h2buf[2][H2];
    __shared__ int l2_done;   // last step whose ring slot L2 has fully released

    const bool isL1 = tid >= NT_L2;   // L1 in HIGH tids -> arbiter priority

    if (tid == 0) l2_done = -1;
    if (isL1 && ((tid - NT_L2) & 1)) h1ring[RING - 1][(tid - NT_L2) >> 1] = 0.0f; // h1(-1)=0
    if (!isL1 && ((tid & 3) == 0)) h2buf[0][tid >> 2] = 0.0f;                     // h2(-1)=0
    __syncthreads();

    if (isL1) {
        // ======== Layer 1 (critical path, high-wid warps): 2 gates per thread ========
        const int l   = tid - NT_L2;
        const int u   = l >> 1;
        const int par = l & 1;
        const int rowA = par * H1 + u;        // par0: i, par1: f
        const int rowB = (2 + par) * H1 + u;  // par0: g, par1: o

        const float bS = par ? 0.5f : 1.0f;   // gateB: g->tanh, o->sigmoid
        const float bA = par ? 0.5f : 1.0f;
        const float bB = par ? 0.5f : 0.0f;

        ull wA[32], wB[32], xA0, xA1, xB0, xB1;
        {
            const float2* whhA = reinterpret_cast<const float2*>(W_hh1 + rowA * H1);
            const float2* whhB = reinterpret_cast<const float2*>(W_hh1 + rowB * H1);
            #pragma unroll
            for (int k = 0; k < 32; ++k) {
                float2 v = whhA[k]; wA[k] = pk2(v.x, v.y);
                float2 w = whhB[k]; wB[k] = pk2(w.x, w.y);
            }
            const float2* wihA = reinterpret_cast<const float2*>(W_ih1 + rowA * INPUT_DIM);
            const float2* wihB = reinterpret_cast<const float2*>(W_ih1 + rowB * INPUT_DIM);
            float2 v;
            v = wihA[0]; xA0 = pk2(v.x, v.y);
            v = wihA[1]; xA1 = pk2(v.x, v.y);
            v = wihB[0]; xB0 = pk2(v.x, v.y);
            v = wihB[1]; xB1 = pk2(v.x, v.y);
        }
        const ull biasAp = pk2(b_ih1[rowA] + b_hh1[rowA], 0.0f);
        const ull biasBp = pk2(b_ih1[rowB] + b_hh1[rowB], 0.0f);

        const float4* xb4 = reinterpret_cast<const float4*>(x + (size_t)b * SEQ * INPUT_DIM);
        float c = 0.0f;          // valid in par==1 lanes
        int consumed = -1;
        float4 xv = __ldg(xb4);  // x(0)

        #pragma unroll 1
        for (int t = 0; t < SEQ; ++t) {
            const int tn = (t + 1 < SEQ) ? (t + 1) : t;
            const float4 xv_next = __ldg(xb4 + tn);

            // backpressure: slot t&7 overwrites h1(t-8); L2 posts flag one step late
            if (t >= RING && consumed < t - RING) {
                do { consumed = ld_acq(&l2_done); } while (consumed < t - RING);
            }

            const ulonglong2* hv =
                reinterpret_cast<const ulonglong2*>(h1ring[(t + RING - 1) & (RING - 1)]);
            const ull xp0 = pk2(xv.x, xv.y);
            const ull xp1 = pk2(xv.z, xv.w);

            ull a0 = biasAp, a1 = 0ull, a2 = 0ull, a3 = 0ull;
            ull d0 = biasBp, d1 = 0ull, d2 = 0ull, d3 = 0ull;
            #pragma unroll
            for (int kk = 0; kk < 8; ++kk) {
                const ulonglong2 hA = hv[2 * kk];
                const ulonglong2 hB = hv[2 * kk + 1];
                a0 = fma2(wA[4 * kk + 0], hA.x, a0);
                d0 = fma2(wB[4 * kk + 0], hA.x, d0);
                a1 = fma2(wA[4 * kk + 1], hA.y, a1);
                d1 = fma2(wB[4 * kk + 1], hA.y, d1);
                a2 = fma2(wA[4 * kk + 2], hB.x, a2);
                d2 = fma2(wB[4 * kk + 2], hB.x, d2);
                a3 = fma2(wA[4 * kk + 3], hB.y, a3);
                d3 = fma2(wB[4 * kk + 3], hB.y, d3);
            }
            a0 = fma2(xA0, xp0, a0); a1 = fma2(xA1, xp1, a1);
            d0 = fma2(xB0, xp0, d0); d1 = fma2(xB1, xp1, d1);
            a0 = add2(add2(a0, a1), add2(a2, a3));
            d0 = add2(add2(d0, d1), add2(d2, d3));
            float alo, ahi, dlo, dhi;
            upk2(a0, alo, ahi); upk2(d0, dlo, dhi);
            const float rawA = alo + ahi;
            const float rawB = dlo + dhi;

            const float sA = __fmaf_rn(0.5f, tanh_approx(0.5f * rawA), 0.5f); // sigmoid
            const float sB = __fmaf_rn(bA, tanh_approx(bS * rawB), bB);

            const float val = sA * sB;                          // par0: i*g
            const float ig  = __shfl_xor_sync(0xffffffffu, val, 1);
            c = __fmaf_rn(sA, c, ig);                           // par1: c=f*c+i*g
            const float h = sB * tanh_approx(c);                // par1: h=o*tanh(c)
            if (par) h1ring[t & (RING - 1)][u] = h;

            bar_sync(1, NT_L1);                 // L1 internal; HW-drains the STS above
            bar_arrive(2 + (t & (RING - 1)), NT_L1 + NT_L2);   // publish h1(t) to L2
            xv = xv_next;
        }
    } else {
        // ======== Layer 2 (low-wid warps): 1 gate per thread ========
        const int u = tid >> 2;
        const int q = tid & 3;
        const float actS = (q == 2) ? 1.0f : 0.5f;
        const float actA = (q == 2) ? 1.0f : 0.5f;
        const float actB = (q == 2) ? 0.0f : 0.5f;

        const int g = q * H2 + u;
        ull w2[48];
        {
            const float2* wih = reinterpret_cast<const float2*>(W_ih2 + g * H1);
            #pragma unroll
            for (int k = 0; k < 32; ++k) { const float2 v = wih[k]; w2[k] = pk2(v.x, v.y); }
            const float2* whh = reinterpret_cast<const float2*>(W_hh2 + g * H2);
            #pragma unroll
            for (int k = 0; k < 16; ++k) { const float2 v = whh[k]; w2[32 + k] = pk2(v.x, v.y); }
        }
        const ull biasp = pk2(b_ih2[g] + b_hh2[g], 0.0f);
        float* outb = out + (size_t)b * SEQ * H2;

        float c = 0.0f;

        #pragma unroll 1
        for (int t = 0; t < SEQ; ++t) {
            // wait for h1(t); also orders h2buf writes from step t-1 (all L2 block here)
            bar_sync(2 + (t & (RING - 1)), NT_L1 + NT_L2);
            // all L2 threads have passed step t-1's reads -> release slot t-1
            if (tid == 0) st_rel(&l2_done, t - 1);

            const ulonglong2* hv = reinterpret_cast<const ulonglong2*>(h1ring[t & (RING - 1)]);
            const ulonglong2* gv = reinterpret_cast<const ulonglong2*>(h2buf[t & 1]);

            ull a0 = biasp, a1 = 0ull, a2 = 0ull, a3 = 0ull;
            #pragma unroll
            for (int kk = 0; kk < 8; ++kk) {
                const ulonglong2 hA = hv[2 * kk];
                const ulonglong2 hB = hv[2 * kk + 1];
                a0 = fma2(w2[4 * kk + 0], hA.x, a0);
                a1 = fma2(w2[4 * kk + 1], hA.y, a1);
                a2 = fma2(w2[4 * kk + 2], hB.x, a2);
                a3 = fma2(w2[4 * kk + 3], hB.y, a3);
            }
            #pragma unroll
            for (int kk = 0; kk < 4; ++kk) {
                const ulonglong2 hA = gv[2 * kk];
                const ulonglong2 hB = gv[2 * kk + 1];
                a0 = fma2(w2[32 + 4 * kk + 0], hA.x, a0);
                a1 = fma2(w2[32 + 4 * kk + 1], hA.y, a1);
                a2 = fma2(w2[32 + 4 * kk + 2], hB.x, a2);
                a3 = fma2(w2[32 + 4 * kk + 3], hB.y, a3);
            }
            a0 = add2(add2(a0, a1), add2(a2, a3));
            float lo, hi; upk2(a0, lo, hi);
            const float raw = lo + hi;

            const float act = __fmaf_rn(actA, tanh_approx(actS * raw), actB);
            const float v1 = __shfl_xor_sync(0xffffffffu, act, 1);
            const float v2 = __shfl_xor_sync(0xffffffffu, act, 2);
            const float v3 = __shfl_xor_sync(0xffffffffu, act, 3);
            c = __fmaf_rn(v1, c, act * v2);
            const float h = v3 * tanh_approx(c);

            if (q == 0) {
                h2buf[(t + 1) & 1][u] = h;
                outb[(size_t)t * H2 + u] = h;
            }
        }
    }
}

extern "C" void kernel_launch(void* const* d_in, const int* in_sizes, int n_in,
                              void* d_out, int out_size) {
    const float* x     = (const float*)d_in[0];
    const float* W_ih1 = (const float*)d_in[1];
    const float* W_hh1 = (const float*)d_in[2];
    const float* b_ih1 = (const float*)d_in[3];
    const float* b_hh1 = (const float*)d_in[4];
    const float* W_ih2 = (const float*)d_in[5];
    const float* W_hh2 = (const float*)d_in[6];
    const float* b_ih2 = (const float*)d_in[7];
    const float* b_hh2 = (const float*)d_in[8];
    float* out = (float*)d_out;

    lstm2_kernel<<<BATCH, NTHREADS>>>(x, W_ih1, W_hh1, b_ih1, b_hh1,
                                      W_ih2, W_hh2, b_ih2, b_hh2, out);
}

// round 11
// speedup vs baseline: 2.0058x; 1.0129x over previous
#include <cuda_runtime.h>
#include <cuda_bf16.h>

#define INPUT_DIM 4
#define H1 64
#define H2 32
#define BATCH 64
#define SEQ 4096

#define NT_L2 128           // tids 0..127   (low wid)
#define NT_L1 128           // tids 128..255 (high wid -> arbiter priority; critical path)
#define NTHREADS (NT_L1 + NT_L2)
#define RING 4              // slot s <-> named barrier id 2+s (joint, count 256)

typedef unsigned long long ull;

// ---- packed f32x2 helpers ----
__device__ __forceinline__ ull pk2(float a, float b) {
    ull r; asm("mov.b64 %0, {%1, %2};" : "=l"(r) : "f"(a), "f"(b)); return r;
}
__device__ __forceinline__ void upk2(ull v, float& a, float& b) {
    asm("mov.b64 {%0, %1}, %2;" : "=f"(a), "=f"(b) : "l"(v));
}
__device__ __forceinline__ ull fma2(ull a, ull b, ull c) {
    ull d; asm("fma.rn.f32x2 %0, %1, %2, %3;" : "=l"(d) : "l"(a), "l"(b), "l"(c)); return d;
}
__device__ __forceinline__ ull add2(ull a, ull b) {
    ull d; asm("add.rn.f32x2 %0, %1, %2;" : "=l"(d) : "l"(a), "l"(b)); return d;
}
__device__ __forceinline__ float tanh_approx(float x) {
    float y; asm("tanh.approx.f32 %0, %1;" : "=f"(y) : "f"(x)); return y;
}
__device__ __forceinline__ void bar_sync(int id, int cnt) {
    asm volatile("bar.sync %0, %1;" :: "r"(id), "r"(cnt) : "memory");
}

__global__ void __launch_bounds__(NTHREADS, 1)
lstm2_kernel(const float* __restrict__ x,
             const float* __restrict__ W_ih1, const float* __restrict__ W_hh1,
             const float* __restrict__ b_ih1, const float* __restrict__ b_hh1,
             const float* __restrict__ W_ih2, const float* __restrict__ W_hh2,
             const float* __restrict__ b_ih2, const float* __restrict__ b_hh2,
             float* __restrict__ out)
{
    const int b   = blockIdx.x;
    const int tid = threadIdx.x;

    __shared__ __align__(16) float h1ring[RING][H1];
    __shared__ __align__(16) float h2buf[2][H2];

    const bool isL1 = tid >= NT_L2;   // L1 in HIGH tids -> arbiter priority

    if (isL1 && ((tid - NT_L2) & 1)) h1ring[RING - 1][(tid - NT_L2) >> 1] = 0.0f; // h1(-1)=0
    if (!isL1 && ((tid & 3) == 0)) h2buf[0][tid >> 2] = 0.0f;                     // h2(-1)=0
    __syncthreads();

    if (isL1) {
        // ======== Layer 1 (critical path, high-wid warps): 2 gates per thread ========
        // step t: read h1(t-1) from slot (t+RING-1)&3, write h1(t) to slot t&3,
        //         then joint bar.sync on barrier 2+(t&3) with L2.
        const int l   = tid - NT_L2;
        const int u   = l >> 1;
        const int par = l & 1;
        const int rowA = par * H1 + u;        // par0: i, par1: f
        const int rowB = (2 + par) * H1 + u;  // par0: g, par1: o

        const float bS = par ? 0.5f : 1.0f;   // gateB: g->tanh, o->sigmoid
        const float bA = par ? 0.5f : 1.0f;
        const float bB = par ? 0.5f : 0.0f;

        ull wA[32], wB[32], xA0, xA1, xB0, xB1;
        {
            const float2* whhA = reinterpret_cast<const float2*>(W_hh1 + rowA * H1);
            const float2* whhB = reinterpret_cast<const float2*>(W_hh1 + rowB * H1);
            #pragma unroll
            for (int k = 0; k < 32; ++k) {
                float2 v = whhA[k]; wA[k] = pk2(v.x, v.y);
                float2 w = whhB[k]; wB[k] = pk2(w.x, w.y);
            }
            const float2* wihA = reinterpret_cast<const float2*>(W_ih1 + rowA * INPUT_DIM);
            const float2* wihB = reinterpret_cast<const float2*>(W_ih1 + rowB * INPUT_DIM);
            float2 v;
            v = wihA[0]; xA0 = pk2(v.x, v.y);
            v = wihA[1]; xA1 = pk2(v.x, v.y);
            v = wihB[0]; xB0 = pk2(v.x, v.y);
            v = wihB[1]; xB1 = pk2(v.x, v.y);
        }
        const ull biasAp = pk2(b_ih1[rowA] + b_hh1[rowA], 0.0f);
        const ull biasBp = pk2(b_ih1[rowB] + b_hh1[rowB], 0.0f);

        const float4* xb4 = reinterpret_cast<const float4*>(x + (size_t)b * SEQ * INPUT_DIM);
        float c = 0.0f;          // valid in par==1 lanes
        float4 xv = __ldg(xb4);  // x(0)

        #pragma unroll 1
        for (int t = 0; t < SEQ; ++t) {
            const int tn = (t + 1 < SEQ) ? (t + 1) : t;
            const float4 xv_next = __ldg(xb4 + tn);

            const ulonglong2* hv =
                reinterpret_cast<const ulonglong2*>(h1ring[(t + RING - 1) & (RING - 1)]);
            const ull xp0 = pk2(xv.x, xv.y);
            const ull xp1 = pk2(xv.z, xv.w);

            ull a0 = biasAp, a1 = 0ull, a2 = 0ull, a3 = 0ull;
            ull d0 = biasBp, d1 = 0ull, d2 = 0ull, d3 = 0ull;
            #pragma unroll
            for (int kk = 0; kk < 8; ++kk) {
                const ulonglong2 hA = hv[2 * kk];
                const ulonglong2 hB = hv[2 * kk + 1];
                a0 = fma2(wA[4 * kk + 0], hA.x, a0);
                d0 = fma2(wB[4 * kk + 0], hA.x, d0);
                a1 = fma2(wA[4 * kk + 1], hA.y, a1);
                d1 = fma2(wB[4 * kk + 1], hA.y, d1);
                a2 = fma2(wA[4 * kk + 2], hB.x, a2);
                d2 = fma2(wB[4 * kk + 2], hB.x, d2);
                a3 = fma2(wA[4 * kk + 3], hB.y, a3);
                d3 = fma2(wB[4 * kk + 3], hB.y, d3);
            }
            a0 = fma2(xA0, xp0, a0); a1 = fma2(xA1, xp1, a1);
            d0 = fma2(xB0, xp0, d0); d1 = fma2(xB1, xp1, d1);
            a0 = add2(add2(a0, a1), add2(a2, a3));
            d0 = add2(add2(d0, d1), add2(d2, d3));
            float alo, ahi, dlo, dhi;
            upk2(a0, alo, ahi); upk2(d0, dlo, dhi);
            const float rawA = alo + ahi;
            const float rawB = dlo + dhi;

            const float sA = __fmaf_rn(0.5f, tanh_approx(0.5f * rawA), 0.5f); // sigmoid
            const float sB = __fmaf_rn(bA, tanh_approx(bS * rawB), bB);

            const float val = sA * sB;                          // par0: i*g
            const float ig  = __shfl_xor_sync(0xffffffffu, val, 1);
            c = __fmaf_rn(sA, c, ig);                           // par1: c=f*c+i*g
            const float h = sB * tanh_approx(c);                // par1: h=o*tanh(c)
            if (par) h1ring[t & (RING - 1)][u] = h;

            // single joint slot barrier: publishes h1(t), orders L1-internal reuse,
            // and enforces ring backpressure (see proof in theory).
            bar_sync(2 + (t & (RING - 1)), NTHREADS);
            xv = xv_next;
        }
    } else {
        // ======== Layer 2 (low-wid warps): 1 gate per thread ========
        const int u = tid >> 2;
        const int q = tid & 3;
        const float actS = (q == 2) ? 1.0f : 0.5f;
        const float actA = (q == 2) ? 1.0f : 0.5f;
        const float actB = (q == 2) ? 0.0f : 0.5f;

        const int g = q * H2 + u;
        ull w2[48];
        {
            const float2* wih = reinterpret_cast<const float2*>(W_ih2 + g * H1);
            #pragma unroll
            for (int k = 0; k < 32; ++k) { const float2 v = wih[k]; w2[k] = pk2(v.x, v.y); }
            const float2* whh = reinterpret_cast<const float2*>(W_hh2 + g * H2);
            #pragma unroll
            for (int k = 0; k < 16; ++k) { const float2 v = whh[k]; w2[32 + k] = pk2(v.x, v.y); }
        }
        const ull biasp = pk2(b_ih2[g] + b_hh2[g], 0.0f);
        float* outb = out + (size_t)b * SEQ * H2;

        float c = 0.0f;

        #pragma unroll 1
        for (int t = 0; t < SEQ; ++t) {
            // joint slot barrier: after this, h1(t) is visible; also orders our
            // h2buf[(t)&1] writes from step t-1 against this step's reads.
            bar_sync(2 + (t & (RING - 1)), NTHREADS);

            const ulonglong2* hv = reinterpret_cast<const ulonglong2*>(h1ring[t & (RING - 1)]);
            const ulonglong2* gv = reinterpret_cast<const ulonglong2*>(h2buf[t & 1]);

            ull a0 = biasp, a1 = 0ull, a2 = 0ull, a3 = 0ull;
            #pragma unroll
            for (int kk = 0; kk < 8; ++kk) {
                const ulonglong2 hA = hv[2 * kk];
                const ulonglong2 hB = hv[2 * kk + 1];
                a0 = fma2(w2[4 * kk + 0], hA.x, a0);
                a1 = fma2(w2[4 * kk + 1], hA.y, a1);
                a2 = fma2(w2[4 * kk + 2], hB.x, a2);
                a3 = fma2(w2[4 * kk + 3], hB.y, a3);
            }
            #pragma unroll
            for (int kk = 0; kk < 4; ++kk) {
                const ulonglong2 hA = gv[2 * kk];
                const ulonglong2 hB = gv[2 * kk + 1];
                a0 = fma2(w2[32 + 4 * kk + 0], hA.x, a0);
                a1 = fma2(w2[32 + 4 * kk + 1], hA.y, a1);
                a2 = fma2(w2[32 + 4 * kk + 2], hB.x, a2);
                a3 = fma2(w2[32 + 4 * kk + 3], hB.y, a3);
            }
            a0 = add2(add2(a0, a1), add2(a2, a3));
            float lo, hi; upk2(a0, lo, hi);
            const float raw = lo + hi;

            const float act = __fmaf_rn(actA, tanh_approx(actS * raw), actB);
            const float v1 = __shfl_xor_sync(0xffffffffu, act, 1);
            const float v2 = __shfl_xor_sync(0xffffffffu, act, 2);
            const float v3 = __shfl_xor_sync(0xffffffffu, act, 3);
            c = __fmaf_rn(v1, c, act * v2);
            const float h = v3 * tanh_approx(c);

            if (q == 0) {
                h2buf[(t + 1) & 1][u] = h;
                outb[(size_t)t * H2 + u] = h;
            }
        }
    }
}

extern "C" void kernel_launch(void* const* d_in, const int* in_sizes, int n_in,
                              void* d_out, int out_size) {
    const float* x     = (const float*)d_in[0];
    const float* W_ih1 = (const float*)d_in[1];
    const float* W_hh1 = (const float*)d_in[2];
    const float* b_ih1 = (const float*)d_in[3];
    const float* b_hh1 = (const float*)d_in[4];
    const float* W_ih2 = (const float*)d_in[5];
    const float* W_hh2 = (const float*)d_in[6];
    const float* b_ih2 = (const float*)d_in[7];
    const float* b_hh2 = (const float*)d_in[8];
    float* out = (float*)d_out;

    lstm2_kernel<<<BATCH, NTHREADS>>>(x, W_ih1, W_hh1, b_ih1, b_hh1,
                                      W_ih2, W_hh2, b_ih2, b_hh2, out);
}